// round 6
// baseline (speedup 1.0000x reference)
#include <cuda_runtime.h>
#include <cuda_fp16.h>
#include <math.h>

// ---------------- problem constants (fixed by the dataset) ----------------
#define NODES 100000
#define FEAT  64
#define EDGES 800000
#define SAMP  25000
#define HID   128

// ---------------- scratch (device globals; no allocation) ----------------
__device__ float  d_q [(size_t)NODES * 128];   // W1^T x + b  (fp32, per-target)
__device__ __half d_pv[(size_t)NODES * 128];   // W2^T x      (fp16, per-source, hot stream)
__device__ float  d_agg[(size_t)NODES * 128];  // per-node max-aggregated activations
__device__ int    d_cnt[NODES];
__device__ int    d_off[NODES];
__device__ int    d_cur[NODES];
__device__ int    d_src[EDGES];

// packed f32x2 FMA (sm_100+): c = a*b + c elementwise on a 64-bit pair
#define FMA2(c, a, b) asm("fma.rn.f32x2 %0, %1, %2, %3;" \
                          : "=l"(c) : "l"(a), "l"(b), "l"(c))

// ---------------- counting sort of edges by target node ----------------
__global__ void k_zero_cnt(int n) {
    int i = blockIdx.x * blockDim.x + threadIdx.x;
    if (i < n) d_cnt[i] = 0;
}

__global__ void k_hist(const int* __restrict__ row, int E) {
    int i = blockIdx.x * blockDim.x + threadIdx.x;
    if (i < E) atomicAdd(&d_cnt[row[i]], 1);
}

// single-block fused scan: 1024 threads x 98 contiguous elements each
#define SCAN_CHUNK 98
__global__ void k_scan() {
    __shared__ int sm[1024];
    int t = threadIdx.x;
    int beg = t * SCAN_CHUNK;
    int end = beg + SCAN_CHUNK;
    if (end > NODES) end = NODES;
    int s = 0;
    for (int i = beg; i < end; i++) s += d_cnt[i];
    sm[t] = s;
    __syncthreads();
    for (int d = 1; d < 1024; d <<= 1) {
        int v = 0;
        if (t >= d) v = sm[t - d];
        __syncthreads();
        if (t >= d) sm[t] += v;
        __syncthreads();
    }
    int run = (t == 0) ? 0 : sm[t - 1];
    for (int i = beg; i < end; i++) {
        int c = d_cnt[i];
        d_off[i] = run;
        d_cur[i] = run;
        run += c;
    }
}

__global__ void k_scatter(const int* __restrict__ col, const int* __restrict__ row, int E) {
    int i = blockIdx.x * blockDim.x + threadIdx.x;
    if (i < E) {
        int t = row[i];
        int p = atomicAdd(&d_cur[t], 1);
        d_src[p] = col[i];
    }
}

// ---------------- per-node precompute GEMM: [N,64] x [64,256] ----------------
// B[k][j] = (j<128) ? W[k][j] : W[64+k][j-128]; bias added to cols < 128.
// k-pair-interleaved smem (FFMA2 operands naturally packed along k):
//   As2[k2][m] float2 = { x[m][2k2],  x[m][2k2+1] }   (32 x 64 pairs, 16 KB)
//   Bs2[k2][j] float2 = { B[2k2][j],  B[2k2+1][j] }   (32 x 256 pairs, 64 KB)
// 512 threads: per-thread tile 8 rows x 4 cols -> 32 f32x2 accs (64 regs),
// no spills (round-4 8x8 tile needed 128 acc regs and spilled).
#define GEMM_SMEM ((4096 + 16384) * 4)

__global__ void __launch_bounds__(512, 1)
k_gemm(const float* __restrict__ x, const float* __restrict__ Wm,
       const float* __restrict__ bv, int N) {
    extern __shared__ float smem[];
    float* As2 = smem;           // 4096 floats
    float* Bs2 = smem + 4096;    // 16384 floats
    int tid = threadIdx.x;       // 512 threads
    int row0 = blockIdx.x * 64;

    // ---- fill A tile (64 rows x 64 feats), k-pair interleaved ----
    {
        int r = tid >> 3;                    // 0..63
        bool ok = (row0 + r) < N;
        const float* xp = x + (size_t)(row0 + r) * FEAT;
#pragma unroll
        for (int i = 0; i < 2; i++) {
            int c = (tid & 7) * 8 + i * 4;   // feature base, mult of 4
            float4 v = ok ? *(const float4*)(xp + c) : make_float4(0.f, 0.f, 0.f, 0.f);
            int k2a = c >> 1;                // pair index for (c, c+1)
            *(float2*)&As2[(k2a * 64 + r) * 2]       = make_float2(v.x, v.y);
            *(float2*)&As2[((k2a + 1) * 64 + r) * 2] = make_float2(v.z, v.w);
        }
    }
    // ---- fill B tile (64 x 256), k-pair interleaved ----
    {
#pragma unroll
        for (int it = 0; it < 4; it++) {
            int v = tid + 512 * it;          // 0..2047 slots, 8 floats each
            int k2 = v >> 6;                 // 0..31
            int j0 = (v & 63) * 4;           // 0..252
            const float *r0p, *r1p;
            if (j0 < 128) {
                r0p = Wm + (2 * k2) * 128 + j0;
                r1p = Wm + (2 * k2 + 1) * 128 + j0;
            } else {
                r0p = Wm + (64 + 2 * k2) * 128 + (j0 - 128);
                r1p = Wm + (65 + 2 * k2) * 128 + (j0 - 128);
            }
            float4 lo = *(const float4*)r0p;
            float4 hi = *(const float4*)r1p;
            float* dst = Bs2 + (k2 * 256 + j0) * 2;
            ((float4*)dst)[0] = make_float4(lo.x, hi.x, lo.y, hi.y);
            ((float4*)dst)[1] = make_float4(lo.z, hi.z, lo.w, hi.w);
        }
    }
    __syncthreads();

    int tm = tid >> 6;   // 0..7  -> rows tm*8..tm*8+7 (warp-uniform: A broadcast)
    int tn = tid & 63;   // 0..63 -> cols tn + 64*jj (lane-contiguous B reads)

    unsigned long long acc[8][4];
#pragma unroll
    for (int i = 0; i < 8; i++)
#pragma unroll
        for (int j = 0; j < 4; j++) acc[i][j] = 0ull;

    const unsigned long long* bBase = (const unsigned long long*)Bs2 + tn;

#pragma unroll 2
    for (int k2 = 0; k2 < 32; k2++) {
        unsigned long long Ar[8], Br[4];
        const ulonglong2* apu = (const ulonglong2*)(As2 + k2 * 128 + tm * 16);
        ulonglong2 u0 = apu[0], u1 = apu[1], u2 = apu[2], u3 = apu[3];
        Ar[0] = u0.x; Ar[1] = u0.y; Ar[2] = u1.x; Ar[3] = u1.y;
        Ar[4] = u2.x; Ar[5] = u2.y; Ar[6] = u3.x; Ar[7] = u3.y;
        const unsigned long long* bp = bBase + k2 * 256;
#pragma unroll
        for (int jj = 0; jj < 4; jj++) Br[jj] = bp[jj * 64];
#pragma unroll
        for (int i = 0; i < 8; i++)
#pragma unroll
            for (int j = 0; j < 4; j++) FMA2(acc[i][j], Ar[i], Br[j]);
    }

    // cols: jj=0 -> tn, jj=1 -> 64+tn (both q, biased); jj=2,3 -> pv half
    float bias0 = bv[tn], bias1 = bv[64 + tn];

#pragma unroll
    for (int i = 0; i < 8; i++) {
        int r = row0 + tm * 8 + i;
        if (r < N) {
            float lo, hi, s0, s1, s2, s3;
            asm("mov.b64 {%0, %1}, %2;" : "=f"(lo), "=f"(hi) : "l"(acc[i][0]));
            s0 = lo + hi;
            asm("mov.b64 {%0, %1}, %2;" : "=f"(lo), "=f"(hi) : "l"(acc[i][1]));
            s1 = lo + hi;
            asm("mov.b64 {%0, %1}, %2;" : "=f"(lo), "=f"(hi) : "l"(acc[i][2]));
            s2 = lo + hi;
            asm("mov.b64 {%0, %1}, %2;" : "=f"(lo), "=f"(hi) : "l"(acc[i][3]));
            s3 = lo + hi;
            d_q[(size_t)r * 128 + tn]       = s0 + bias0;
            d_q[(size_t)r * 128 + 64 + tn]  = s1 + bias1;
            d_pv[(size_t)r * 128 + tn]      = __float2half(s2);
            d_pv[(size_t)r * 128 + 64 + tn] = __float2half(s3);
        }
    }
}

// ---------------- edge aggregation: one warp per target node ----------------
__device__ __forceinline__ float angle3(float ax, float ay, float az,
                                        float bx, float by, float bz) {
    float cx = ay * bz - az * by;
    float cy = az * bx - ax * bz;
    float cz = ax * by - ay * bx;
    float cn = sqrtf(cx * cx + cy * cy + cz * cz);
    float d = ax * bx + ay * by + az * bz;
    return atan2f(cn, d);
}

__global__ void k_agg(const float* __restrict__ pos, const float* __restrict__ nor,
                      const float* __restrict__ Wm, int N) {
    int w = (blockIdx.x * blockDim.x + threadIdx.x) >> 5;
    if (w >= N) return;
    int cnt = d_cnt[w];
    if (cnt == 0) return;
    int lane = threadIdx.x & 31;
    int start = d_off[w];
    int end = start + cnt;
    int col = lane * 4;

    float4 q  = *(const float4*)&d_q[(size_t)w * 128 + col];    // includes bias
    float4 w0 = *(const float4*)&Wm[128 * 128 + col];           // ppf weight rows
    float4 w1 = *(const float4*)&Wm[129 * 128 + col];
    float4 w2 = *(const float4*)&Wm[130 * 128 + col];
    float4 w3 = *(const float4*)&Wm[131 * 128 + col];
    float ptx = pos[3 * w], pty = pos[3 * w + 1], ptz = pos[3 * w + 2];
    float ntx = nor[3 * w], nty = nor[3 * w + 1], ntz = nor[3 * w + 2];
    float4 m = make_float4(0.f, 0.f, 0.f, 0.f);  // relu floor + empty handling

    for (int base = start; base < end; base += 32) {
        int j = base + lane;
        int s = 0;
        float f0 = 0.f, f1 = 0.f, f2 = 0.f, f3 = 0.f;
        if (j < end) {
            s = d_src[j];
            float px = pos[3 * s] - ptx;
            float py = pos[3 * s + 1] - pty;
            float pz = pos[3 * s + 2] - ptz;
            float nsx = nor[3 * s], nsy = nor[3 * s + 1], nsz = nor[3 * s + 2];
            f0 = sqrtf(px * px + py * py + pz * pz);
            f1 = angle3(ntx, nty, ntz, px, py, pz);    // angle(n1, pseudo)
            f2 = angle3(nsx, nsy, nsz, px, py, pz);    // angle(n0, pseudo)
            f3 = angle3(ntx, nty, ntz, nsx, nsy, nsz); // angle(n1, n0)
        }
        int c32 = end - base;
        if (c32 > 32) c32 = 32;
        for (int i = 0; i < c32; i++) {
            int si  = __shfl_sync(0xffffffffu, s, i);
            float g0 = __shfl_sync(0xffffffffu, f0, i);
            float g1 = __shfl_sync(0xffffffffu, f1, i);
            float g2 = __shfl_sync(0xffffffffu, f2, i);
            float g3 = __shfl_sync(0xffffffffu, f3, i);
            uint2 hv = *(const uint2*)&d_pv[(size_t)si * 128 + col];  // 4 halves, 8B
            float2 p01 = __half22float2(*(const __half2*)&hv.x);
            float2 p23 = __half22float2(*(const __half2*)&hv.y);
            float z0 = q.x + p01.x, z1 = q.y + p01.y;
            float z2 = q.z + p23.x, z3 = q.w + p23.y;
            z0 = fmaf(g0, w0.x, z0); z1 = fmaf(g0, w0.y, z1); z2 = fmaf(g0, w0.z, z2); z3 = fmaf(g0, w0.w, z3);
            z0 = fmaf(g1, w1.x, z0); z1 = fmaf(g1, w1.y, z1); z2 = fmaf(g1, w1.z, z2); z3 = fmaf(g1, w1.w, z3);
            z0 = fmaf(g2, w2.x, z0); z1 = fmaf(g2, w2.y, z1); z2 = fmaf(g2, w2.z, z2); z3 = fmaf(g2, w2.w, z3);
            z0 = fmaf(g3, w3.x, z0); z1 = fmaf(g3, w3.y, z1); z2 = fmaf(g3, w3.z, z2); z3 = fmaf(g3, w3.w, z3);
            m.x = fmaxf(m.x, z0); m.y = fmaxf(m.y, z1);
            m.z = fmaxf(m.z, z2); m.w = fmaxf(m.w, z3);
        }
    }
    *(float4*)&d_agg[(size_t)w * 128 + col] = m;
}

// ---------------- gather: out[s] = agg[idx[s]] (0 if no edges), pos_out ----------------
__global__ void k_gather(const float* __restrict__ pos, const int* __restrict__ idx,
                         float* __restrict__ out, int S) {
    int s = blockIdx.x;
    int h = threadIdx.x;  // 128
    int t = idx[s];
    float v = d_cnt[t] ? d_agg[(size_t)t * 128 + h] : 0.f;
    out[(size_t)s * 128 + h] = v;
    if (h < 3) out[(size_t)S * 128 + (size_t)s * 3 + h] = pos[3 * t + h];
}

// ---------------- launch ----------------
extern "C" void kernel_launch(void* const* d_in, const int* in_sizes, int n_in,
                              void* d_out, int out_size) {
    const float *x = 0, *pos = 0, *nor = 0, *Wm = 0, *bv = 0;
    const int *edge = 0, *idx = 0;
    for (int i = 0; i < n_in; i++) {
        int sz = in_sizes[i];
        if (sz == NODES * FEAT) x = (const float*)d_in[i];
        else if (sz == NODES * 3) { if (!pos) pos = (const float*)d_in[i]; else nor = (const float*)d_in[i]; }
        else if (sz == (2 * FEAT + 4) * HID) Wm = (const float*)d_in[i];
        else if (sz == HID) bv = (const float*)d_in[i];
        else if (sz == 2 * EDGES) edge = (const int*)d_in[i];
        else if (sz == SAMP) idx = (const int*)d_in[i];
    }
    const int* ecol = edge;          // e0 (sources)
    const int* erow = edge + EDGES;  // e1 (targets)

    k_zero_cnt<<<(NODES + 255) / 256, 256>>>(NODES);
    k_hist<<<(EDGES + 255) / 256, 256>>>(erow, EDGES);
    k_scan<<<1, 1024>>>();
    k_scatter<<<(EDGES + 255) / 256, 256>>>(ecol, erow, EDGES);

    cudaFuncSetAttribute(k_gemm, cudaFuncAttributeMaxDynamicSharedMemorySize, GEMM_SMEM);
    k_gemm<<<(NODES + 63) / 64, 256 * 2, GEMM_SMEM>>>(x, Wm, bv, NODES);

    k_agg<<<(NODES + 7) / 8, 256>>>(pos, nor, Wm, NODES);
    k_gather<<<SAMP, 128>>>(pos, idx, (float*)d_out, SAMP);
}

// round 7
// speedup vs baseline: 1.6943x; 1.6943x over previous
#include <cuda_runtime.h>
#include <cuda_fp16.h>
#include <math.h>

// ---------------- problem constants (fixed by the dataset) ----------------
#define NODES 100000
#define FEAT  64
#define EDGES 800000
#define SAMP  25000
#define HID   128

// ---------------- scratch (device globals; no allocation) ----------------
__device__ float  d_q [(size_t)NODES * 128];   // W1^T x + b  (fp32, target nodes only)
__device__ __half d_pv[(size_t)NODES * 128];   // W2^T x      (fp16, per-source, hot stream)
__device__ float  d_agg[(size_t)NODES * 128];  // per-node max-aggregated activations
__device__ int    d_cnt[NODES];
__device__ int    d_off[NODES];
__device__ int    d_cur[NODES];
__device__ int    d_src[EDGES];
__device__ int    d_tlist[NODES];              // compact list of nodes with cnt>0
__device__ int    d_ntl;                       // its length

// ---------------- counting sort of edges by target node ----------------
__global__ void k_zero_cnt(int n) {
    int i = blockIdx.x * blockDim.x + threadIdx.x;
    if (i < n) d_cnt[i] = 0;
    if (i == 0) d_ntl = 0;
}

__global__ void k_hist(const int* __restrict__ row, int E) {
    int i = blockIdx.x * blockDim.x + threadIdx.x;
    if (i < E) atomicAdd(&d_cnt[row[i]], 1);
}

// single-block fused scan: 1024 threads x 98 contiguous elements each.
// Also builds the compact target-node list (order nondeterministic, harmless).
#define SCAN_CHUNK 98
__global__ void k_scan() {
    __shared__ int sm[1024];
    int t = threadIdx.x;
    int beg = t * SCAN_CHUNK;
    int end = beg + SCAN_CHUNK;
    if (end > NODES) end = NODES;
    int s = 0;
    for (int i = beg; i < end; i++) s += d_cnt[i];
    sm[t] = s;
    __syncthreads();
    for (int d = 1; d < 1024; d <<= 1) {
        int v = 0;
        if (t >= d) v = sm[t - d];
        __syncthreads();
        if (t >= d) sm[t] += v;
        __syncthreads();
    }
    int run = (t == 0) ? 0 : sm[t - 1];
    for (int i = beg; i < end; i++) {
        int c = d_cnt[i];
        d_off[i] = run;
        d_cur[i] = run;
        run += c;
        if (c > 0) {
            int p = atomicAdd(&d_ntl, 1);
            d_tlist[p] = i;
        }
    }
}

__global__ void k_scatter(const int* __restrict__ col, const int* __restrict__ row, int E) {
    int i = blockIdx.x * blockDim.x + threadIdx.x;
    if (i < E) {
        int t = row[i];
        int p = atomicAdd(&d_cur[t], 1);
        d_src[p] = col[i];
    }
}

// ---------------- GEMM helpers: [tile 64 rows] x [64,128], scalar FFMA ----------------
// smem: As[64 k][68] transposed (17408B) + Bs[64 k][128] (32768B) + tl[64] (256B)
#define GEMM_SMEM ((64 * 68 + 64 * 128 + 64) * 4)

// pv GEMM over ALL nodes: B = W rows [64:128), output fp16 d_pv
__global__ void __launch_bounds__(256)
k_gemm_pv(const float* __restrict__ x, const float* __restrict__ Wm, int N) {
    extern __shared__ float smem[];
    float* As = smem;              // [k*68 + m]
    float* Bs = smem + 64 * 68;    // [k*128 + j]
    int tid = threadIdx.x;
    int row0 = blockIdx.x * 64;

    {   // A tile: 64 rows x 64 feats, transposed
        int r = tid >> 2;
        bool ok = (row0 + r) < N;
        const float* xp = x + (size_t)(row0 + r) * FEAT;
#pragma unroll
        for (int i = 0; i < 4; i++) {
            int c = (tid & 3) * 4 + i * 16;
            float4 v = ok ? *(const float4*)(xp + c) : make_float4(0.f, 0.f, 0.f, 0.f);
            As[(c + 0) * 68 + r] = v.x;
            As[(c + 1) * 68 + r] = v.y;
            As[(c + 2) * 68 + r] = v.z;
            As[(c + 3) * 68 + r] = v.w;
        }
    }
    {   // B tile: W rows [64:128) x 128 cols
#pragma unroll
        for (int i = 0; i < 8; i++) {
            int v = tid + 256 * i;          // 0..2047 float4 slots
            int k = v >> 5;
            int j0 = (v & 31) * 4;
            *(float4*)&Bs[k * 128 + j0] = *(const float4*)(Wm + (64 + k) * 128 + j0);
        }
    }
    __syncthreads();

    int tm = tid >> 5;   // warp id: A reads broadcast
    int tn = tid & 31;   // cols tn*4..tn*4+3
    float acc[8][4];
#pragma unroll
    for (int i = 0; i < 8; i++)
#pragma unroll
        for (int j = 0; j < 4; j++) acc[i][j] = 0.f;

#pragma unroll 4
    for (int k = 0; k < 64; k++) {
        float a[8];
        *(float4*)(a)     = *(const float4*)&As[k * 68 + tm * 8];
        *(float4*)(a + 4) = *(const float4*)&As[k * 68 + tm * 8 + 4];
        float4 b4 = *(const float4*)&Bs[k * 128 + tn * 4];
#pragma unroll
        for (int i = 0; i < 8; i++) {
            acc[i][0] = fmaf(a[i], b4.x, acc[i][0]);
            acc[i][1] = fmaf(a[i], b4.y, acc[i][1]);
            acc[i][2] = fmaf(a[i], b4.z, acc[i][2]);
            acc[i][3] = fmaf(a[i], b4.w, acc[i][3]);
        }
    }

#pragma unroll
    for (int i = 0; i < 8; i++) {
        int r = row0 + tm * 8 + i;
        if (r < N) {
            __half2 h0 = __floats2half2_rn(acc[i][0], acc[i][1]);
            __half2 h1 = __floats2half2_rn(acc[i][2], acc[i][3]);
            *(uint2*)&d_pv[(size_t)r * 128 + tn * 4] = make_uint2(
                *(unsigned*)&h0, *(unsigned*)&h1);
        }
    }
}

// q GEMM over target-node list: B = W rows [0:64), + bias, output fp32 d_q
__global__ void __launch_bounds__(256)
k_gemm_q(const float* __restrict__ x, const float* __restrict__ Wm,
         const float* __restrict__ bv) {
    int ntl = d_ntl;
    int row0 = blockIdx.x * 64;
    if (row0 >= ntl) return;
    extern __shared__ float smem[];
    float* As = smem;
    float* Bs = smem + 64 * 68;
    int*   tl = (int*)(smem + 64 * 68 + 64 * 128);
    int tid = threadIdx.x;

    if (tid < 64) tl[tid] = (row0 + tid < ntl) ? d_tlist[row0 + tid] : -1;
    __syncthreads();

    {   // A tile via row indirection
        int r = tid >> 2;
        int row = tl[r];
        bool ok = row >= 0;
        const float* xp = x + (size_t)(ok ? row : 0) * FEAT;
#pragma unroll
        for (int i = 0; i < 4; i++) {
            int c = (tid & 3) * 4 + i * 16;
            float4 v = ok ? *(const float4*)(xp + c) : make_float4(0.f, 0.f, 0.f, 0.f);
            As[(c + 0) * 68 + r] = v.x;
            As[(c + 1) * 68 + r] = v.y;
            As[(c + 2) * 68 + r] = v.z;
            As[(c + 3) * 68 + r] = v.w;
        }
    }
    {   // B tile: W rows [0:64)
#pragma unroll
        for (int i = 0; i < 8; i++) {
            int v = tid + 256 * i;
            int k = v >> 5;
            int j0 = (v & 31) * 4;
            *(float4*)&Bs[k * 128 + j0] = *(const float4*)(Wm + k * 128 + j0);
        }
    }
    __syncthreads();

    int tm = tid >> 5;
    int tn = tid & 31;
    float acc[8][4];
#pragma unroll
    for (int i = 0; i < 8; i++)
#pragma unroll
        for (int j = 0; j < 4; j++) acc[i][j] = 0.f;

#pragma unroll 4
    for (int k = 0; k < 64; k++) {
        float a[8];
        *(float4*)(a)     = *(const float4*)&As[k * 68 + tm * 8];
        *(float4*)(a + 4) = *(const float4*)&As[k * 68 + tm * 8 + 4];
        float4 b4 = *(const float4*)&Bs[k * 128 + tn * 4];
#pragma unroll
        for (int i = 0; i < 8; i++) {
            acc[i][0] = fmaf(a[i], b4.x, acc[i][0]);
            acc[i][1] = fmaf(a[i], b4.y, acc[i][1]);
            acc[i][2] = fmaf(a[i], b4.z, acc[i][2]);
            acc[i][3] = fmaf(a[i], b4.w, acc[i][3]);
        }
    }

    float4 bias = *(const float4*)&bv[tn * 4];
#pragma unroll
    for (int i = 0; i < 8; i++) {
        int row = tl[tm * 8 + i];
        if (row >= 0) {
            float4 v = make_float4(acc[i][0] + bias.x, acc[i][1] + bias.y,
                                   acc[i][2] + bias.z, acc[i][3] + bias.w);
            *(float4*)&d_q[(size_t)row * 128 + tn * 4] = v;
        }
    }
}

// ---------------- edge aggregation: one warp per target node ----------------
__device__ __forceinline__ float angle3(float ax, float ay, float az,
                                        float bx, float by, float bz) {
    float cx = ay * bz - az * by;
    float cy = az * bx - ax * bz;
    float cz = ax * by - ay * bx;
    float cn = sqrtf(cx * cx + cy * cy + cz * cz);
    float d = ax * bx + ay * by + az * bz;
    return atan2f(cn, d);
}

__global__ void k_agg(const float* __restrict__ pos, const float* __restrict__ nor,
                      const float* __restrict__ Wm, int N) {
    int w = (blockIdx.x * blockDim.x + threadIdx.x) >> 5;
    if (w >= N) return;
    int cnt = d_cnt[w];
    if (cnt == 0) return;
    int lane = threadIdx.x & 31;
    int start = d_off[w];
    int end = start + cnt;
    int col = lane * 4;

    float4 q  = *(const float4*)&d_q[(size_t)w * 128 + col];    // includes bias
    float4 w0 = *(const float4*)&Wm[128 * 128 + col];           // ppf weight rows
    float4 w1 = *(const float4*)&Wm[129 * 128 + col];
    float4 w2 = *(const float4*)&Wm[130 * 128 + col];
    float4 w3 = *(const float4*)&Wm[131 * 128 + col];
    float ptx = pos[3 * w], pty = pos[3 * w + 1], ptz = pos[3 * w + 2];
    float ntx = nor[3 * w], nty = nor[3 * w + 1], ntz = nor[3 * w + 2];
    float4 m = make_float4(0.f, 0.f, 0.f, 0.f);  // relu floor + empty handling

    for (int base = start; base < end; base += 32) {
        int j = base + lane;
        int s = 0;
        float f0 = 0.f, f1 = 0.f, f2 = 0.f, f3 = 0.f;
        if (j < end) {
            s = d_src[j];
            float px = pos[3 * s] - ptx;
            float py = pos[3 * s + 1] - pty;
            float pz = pos[3 * s + 2] - ptz;
            float nsx = nor[3 * s], nsy = nor[3 * s + 1], nsz = nor[3 * s + 2];
            f0 = sqrtf(px * px + py * py + pz * pz);
            f1 = angle3(ntx, nty, ntz, px, py, pz);    // angle(n1, pseudo)
            f2 = angle3(nsx, nsy, nsz, px, py, pz);    // angle(n0, pseudo)
            f3 = angle3(ntx, nty, ntz, nsx, nsy, nsz); // angle(n1, n0)
        }
        int c32 = end - base;
        if (c32 > 32) c32 = 32;
        for (int i = 0; i < c32; i++) {
            int si  = __shfl_sync(0xffffffffu, s, i);
            float g0 = __shfl_sync(0xffffffffu, f0, i);
            float g1 = __shfl_sync(0xffffffffu, f1, i);
            float g2 = __shfl_sync(0xffffffffu, f2, i);
            float g3 = __shfl_sync(0xffffffffu, f3, i);
            uint2 hv = *(const uint2*)&d_pv[(size_t)si * 128 + col];  // 4 halves, 8B
            float2 p01 = __half22float2(*(const __half2*)&hv.x);
            float2 p23 = __half22float2(*(const __half2*)&hv.y);
            float z0 = q.x + p01.x, z1 = q.y + p01.y;
            float z2 = q.z + p23.x, z3 = q.w + p23.y;
            z0 = fmaf(g0, w0.x, z0); z1 = fmaf(g0, w0.y, z1); z2 = fmaf(g0, w0.z, z2); z3 = fmaf(g0, w0.w, z3);
            z0 = fmaf(g1, w1.x, z0); z1 = fmaf(g1, w1.y, z1); z2 = fmaf(g1, w1.z, z2); z3 = fmaf(g1, w1.w, z3);
            z0 = fmaf(g2, w2.x, z0); z1 = fmaf(g2, w2.y, z1); z2 = fmaf(g2, w2.z, z2); z3 = fmaf(g2, w2.w, z3);
            z0 = fmaf(g3, w3.x, z0); z1 = fmaf(g3, w3.y, z1); z2 = fmaf(g3, w3.z, z2); z3 = fmaf(g3, w3.w, z3);
            m.x = fmaxf(m.x, z0); m.y = fmaxf(m.y, z1);
            m.z = fmaxf(m.z, z2); m.w = fmaxf(m.w, z3);
        }
    }
    *(float4*)&d_agg[(size_t)w * 128 + col] = m;
}

// ---------------- gather: out[s] = agg[idx[s]] (0 if no edges), pos_out ----------------
__global__ void k_gather(const float* __restrict__ pos, const int* __restrict__ idx,
                         float* __restrict__ out, int S) {
    int s = blockIdx.x;
    int h = threadIdx.x;  // 128
    int t = idx[s];
    float v = d_cnt[t] ? d_agg[(size_t)t * 128 + h] : 0.f;
    out[(size_t)s * 128 + h] = v;
    if (h < 3) out[(size_t)S * 128 + (size_t)s * 3 + h] = pos[3 * t + h];
}

// ---------------- launch ----------------
extern "C" void kernel_launch(void* const* d_in, const int* in_sizes, int n_in,
                              void* d_out, int out_size) {
    const float *x = 0, *pos = 0, *nor = 0, *Wm = 0, *bv = 0;
    const int *edge = 0, *idx = 0;
    for (int i = 0; i < n_in; i++) {
        int sz = in_sizes[i];
        if (sz == NODES * FEAT) x = (const float*)d_in[i];
        else if (sz == NODES * 3) { if (!pos) pos = (const float*)d_in[i]; else nor = (const float*)d_in[i]; }
        else if (sz == (2 * FEAT + 4) * HID) Wm = (const float*)d_in[i];
        else if (sz == HID) bv = (const float*)d_in[i];
        else if (sz == 2 * EDGES) edge = (const int*)d_in[i];
        else if (sz == SAMP) idx = (const int*)d_in[i];
    }
    const int* ecol = edge;          // e0 (sources)
    const int* erow = edge + EDGES;  // e1 (targets)

    k_zero_cnt<<<(NODES + 255) / 256, 256>>>(NODES);
    k_hist<<<(EDGES + 255) / 256, 256>>>(erow, EDGES);
    k_scan<<<1, 1024>>>();
    k_scatter<<<(EDGES + 255) / 256, 256>>>(ecol, erow, EDGES);

    cudaFuncSetAttribute(k_gemm_pv, cudaFuncAttributeMaxDynamicSharedMemorySize, GEMM_SMEM);
    cudaFuncSetAttribute(k_gemm_q,  cudaFuncAttributeMaxDynamicSharedMemorySize, GEMM_SMEM);
    k_gemm_pv<<<(NODES + 63) / 64, 256, GEMM_SMEM>>>(x, Wm, NODES);
    k_gemm_q <<<(NODES + 63) / 64, 256, GEMM_SMEM>>>(x, Wm, bv);

    k_agg<<<(NODES + 7) / 8, 256>>>(pos, nor, Wm, NODES);
    k_gather<<<SAMP, 128>>>(pos, idx, (float*)d_out, SAMP);
}

// round 8
// speedup vs baseline: 3.0628x; 1.8076x over previous
#include <cuda_runtime.h>
#include <cuda_fp16.h>
#include <math.h>

// ---------------- problem constants (fixed by the dataset) ----------------
#define NODES 100000
#define FEAT  64
#define EDGES 800000
#define SAMP  25000
#define HID   128

// ---------------- scratch (device globals; no allocation) ----------------
__device__ float  d_q [(size_t)NODES * 128];   // W1^T x + b  (fp32, target nodes only)
__device__ __half d_pv[(size_t)NODES * 128];   // W2^T x      (fp16, per-source, hot stream)
__device__ float  d_agg[(size_t)NODES * 128];  // per-node max-aggregated activations
__device__ int    d_cnt[NODES];
__device__ int    d_off[NODES];
__device__ int    d_cur[NODES];
__device__ int    d_src[EDGES];
__device__ int    d_bsum[128];
__device__ int    d_tlist[NODES];              // compact list of nodes with cnt>0
__device__ int    d_ntl;                       // its length

// ---------------- counting sort of edges by target node ----------------
__global__ void k_zero_cnt(int n) {
    int i = blockIdx.x * blockDim.x + threadIdx.x;
    if (i < n) d_cnt[i] = 0;
    if (i == 0) d_ntl = 0;
}

__global__ void k_hist(const int* __restrict__ row, int E) {
    int i = blockIdx.x * blockDim.x + threadIdx.x;
    if (i < E) atomicAdd(&d_cnt[row[i]], 1);
}

__global__ void k_scan1(int n) {  // per-1024-block inclusive scan, block sums out
    __shared__ int sm[1024];
    int i = blockIdx.x * 1024 + threadIdx.x;
    int v = (i < n) ? d_cnt[i] : 0;
    sm[threadIdx.x] = v;
    __syncthreads();
    for (int d = 1; d < 1024; d <<= 1) {
        int t = 0;
        if (threadIdx.x >= d) t = sm[threadIdx.x - d];
        __syncthreads();
        if (threadIdx.x >= d) sm[threadIdx.x] += t;
        __syncthreads();
    }
    if (i < n) d_off[i] = sm[threadIdx.x];            // inclusive for now
    if (threadIdx.x == 1023) d_bsum[blockIdx.x] = sm[1023];
}

__global__ void k_scan2(int nb) {  // exclusive scan of <=128 block sums (1 block)
    __shared__ int sm[128];
    int t = threadIdx.x;
    int v = (t < nb) ? d_bsum[t] : 0;
    sm[t] = v;
    __syncthreads();
    for (int d = 1; d < 128; d <<= 1) {
        int u = 0;
        if (t >= d) u = sm[t - d];
        __syncthreads();
        if (t >= d) sm[t] += u;
        __syncthreads();
    }
    if (t < nb) d_bsum[t] = sm[t] - v;  // exclusive
}

__global__ void k_scan3(int n) {  // finalize offsets + cursor + compact target list
    int i = blockIdx.x * blockDim.x + threadIdx.x;
    if (i < n) {
        int c = d_cnt[i];
        int e = d_off[i] - c + d_bsum[i >> 10];
        d_off[i] = e;
        d_cur[i] = e;
        if (c > 0) {                       // warp-uniform address -> REDUX-aggregated
            int p = atomicAdd(&d_ntl, 1);
            d_tlist[p] = i;
        }
    }
}

__global__ void k_scatter(const int* __restrict__ col, const int* __restrict__ row, int E) {
    int i = blockIdx.x * blockDim.x + threadIdx.x;
    if (i < E) {
        int t = row[i];
        int p = atomicAdd(&d_cur[t], 1);
        d_src[p] = col[i];
    }
}

// ---------------- GEMM helpers: [tile 64 rows] x [64,128], scalar FFMA ----------------
// smem: As[64 k][68] transposed (17408B) + Bs[64 k][128] (32768B) + tl[64] (256B)
#define GEMM_SMEM ((64 * 68 + 64 * 128 + 64) * 4)

// pv GEMM over ALL nodes: B = W rows [64:128), output fp16 d_pv
__global__ void __launch_bounds__(256)
k_gemm_pv(const float* __restrict__ x, const float* __restrict__ Wm, int N) {
    extern __shared__ float smem[];
    float* As = smem;              // [k*68 + m]
    float* Bs = smem + 64 * 68;    // [k*128 + j]
    int tid = threadIdx.x;
    int row0 = blockIdx.x * 64;

    {   // A tile: 64 rows x 64 feats, transposed
        int r = tid >> 2;
        bool ok = (row0 + r) < N;
        const float* xp = x + (size_t)(row0 + r) * FEAT;
#pragma unroll
        for (int i = 0; i < 4; i++) {
            int c = (tid & 3) * 4 + i * 16;
            float4 v = ok ? *(const float4*)(xp + c) : make_float4(0.f, 0.f, 0.f, 0.f);
            As[(c + 0) * 68 + r] = v.x;
            As[(c + 1) * 68 + r] = v.y;
            As[(c + 2) * 68 + r] = v.z;
            As[(c + 3) * 68 + r] = v.w;
        }
    }
    {   // B tile: W rows [64:128) x 128 cols
#pragma unroll
        for (int i = 0; i < 8; i++) {
            int v = tid + 256 * i;          // 0..2047 float4 slots
            int k = v >> 5;
            int j0 = (v & 31) * 4;
            *(float4*)&Bs[k * 128 + j0] = *(const float4*)(Wm + (64 + k) * 128 + j0);
        }
    }
    __syncthreads();

    int tm = tid >> 5;   // warp id: A reads broadcast
    int tn = tid & 31;   // cols tn*4..tn*4+3
    float acc[8][4];
#pragma unroll
    for (int i = 0; i < 8; i++)
#pragma unroll
        for (int j = 0; j < 4; j++) acc[i][j] = 0.f;

#pragma unroll 4
    for (int k = 0; k < 64; k++) {
        float a[8];
        *(float4*)(a)     = *(const float4*)&As[k * 68 + tm * 8];
        *(float4*)(a + 4) = *(const float4*)&As[k * 68 + tm * 8 + 4];
        float4 b4 = *(const float4*)&Bs[k * 128 + tn * 4];
#pragma unroll
        for (int i = 0; i < 8; i++) {
            acc[i][0] = fmaf(a[i], b4.x, acc[i][0]);
            acc[i][1] = fmaf(a[i], b4.y, acc[i][1]);
            acc[i][2] = fmaf(a[i], b4.z, acc[i][2]);
            acc[i][3] = fmaf(a[i], b4.w, acc[i][3]);
        }
    }

#pragma unroll
    for (int i = 0; i < 8; i++) {
        int r = row0 + tm * 8 + i;
        if (r < N) {
            __half2 h0 = __floats2half2_rn(acc[i][0], acc[i][1]);
            __half2 h1 = __floats2half2_rn(acc[i][2], acc[i][3]);
            *(uint2*)&d_pv[(size_t)r * 128 + tn * 4] = make_uint2(
                *(unsigned*)&h0, *(unsigned*)&h1);
        }
    }
}

// q GEMM over target-node list: B = W rows [0:64), + bias, output fp32 d_q
__global__ void __launch_bounds__(256)
k_gemm_q(const float* __restrict__ x, const float* __restrict__ Wm,
         const float* __restrict__ bv) {
    int ntl = d_ntl;
    int row0 = blockIdx.x * 64;
    if (row0 >= ntl) return;
    extern __shared__ float smem[];
    float* As = smem;
    float* Bs = smem + 64 * 68;
    int*   tl = (int*)(smem + 64 * 68 + 64 * 128);
    int tid = threadIdx.x;

    if (tid < 64) tl[tid] = (row0 + tid < ntl) ? d_tlist[row0 + tid] : -1;
    __syncthreads();

    {   // A tile via row indirection
        int r = tid >> 2;
        int row = tl[r];
        bool ok = row >= 0;
        const float* xp = x + (size_t)(ok ? row : 0) * FEAT;
#pragma unroll
        for (int i = 0; i < 4; i++) {
            int c = (tid & 3) * 4 + i * 16;
            float4 v = ok ? *(const float4*)(xp + c) : make_float4(0.f, 0.f, 0.f, 0.f);
            As[(c + 0) * 68 + r] = v.x;
            As[(c + 1) * 68 + r] = v.y;
            As[(c + 2) * 68 + r] = v.z;
            As[(c + 3) * 68 + r] = v.w;
        }
    }
    {   // B tile: W rows [0:64)
#pragma unroll
        for (int i = 0; i < 8; i++) {
            int v = tid + 256 * i;
            int k = v >> 5;
            int j0 = (v & 31) * 4;
            *(float4*)&Bs[k * 128 + j0] = *(const float4*)(Wm + k * 128 + j0);
        }
    }
    __syncthreads();

    int tm = tid >> 5;
    int tn = tid & 31;
    float acc[8][4];
#pragma unroll
    for (int i = 0; i < 8; i++)
#pragma unroll
        for (int j = 0; j < 4; j++) acc[i][j] = 0.f;

#pragma unroll 4
    for (int k = 0; k < 64; k++) {
        float a[8];
        *(float4*)(a)     = *(const float4*)&As[k * 68 + tm * 8];
        *(float4*)(a + 4) = *(const float4*)&As[k * 68 + tm * 8 + 4];
        float4 b4 = *(const float4*)&Bs[k * 128 + tn * 4];
#pragma unroll
        for (int i = 0; i < 8; i++) {
            acc[i][0] = fmaf(a[i], b4.x, acc[i][0]);
            acc[i][1] = fmaf(a[i], b4.y, acc[i][1]);
            acc[i][2] = fmaf(a[i], b4.z, acc[i][2]);
            acc[i][3] = fmaf(a[i], b4.w, acc[i][3]);
        }
    }

    float4 bias = *(const float4*)&bv[tn * 4];
#pragma unroll
    for (int i = 0; i < 8; i++) {
        int row = tl[tm * 8 + i];
        if (row >= 0) {
            float4 v = make_float4(acc[i][0] + bias.x, acc[i][1] + bias.y,
                                   acc[i][2] + bias.z, acc[i][3] + bias.w);
            *(float4*)&d_q[(size_t)row * 128 + tn * 4] = v;
        }
    }
}

// ---------------- edge aggregation: one warp per target node ----------------
__device__ __forceinline__ float angle3(float ax, float ay, float az,
                                        float bx, float by, float bz) {
    float cx = ay * bz - az * by;
    float cy = az * bx - ax * bz;
    float cz = ax * by - ay * bx;
    float cn = sqrtf(cx * cx + cy * cy + cz * cz);
    float d = ax * bx + ay * by + az * bz;
    return atan2f(cn, d);
}

__global__ void k_agg(const float* __restrict__ pos, const float* __restrict__ nor,
                      const float* __restrict__ Wm, int N) {
    int w = (blockIdx.x * blockDim.x + threadIdx.x) >> 5;
    if (w >= N) return;
    int cnt = d_cnt[w];
    if (cnt == 0) return;
    int lane = threadIdx.x & 31;
    int start = d_off[w];
    int end = start + cnt;
    int col = lane * 4;

    float4 q  = *(const float4*)&d_q[(size_t)w * 128 + col];    // includes bias
    float4 w0 = *(const float4*)&Wm[128 * 128 + col];           // ppf weight rows
    float4 w1 = *(const float4*)&Wm[129 * 128 + col];
    float4 w2 = *(const float4*)&Wm[130 * 128 + col];
    float4 w3 = *(const float4*)&Wm[131 * 128 + col];
    float ptx = pos[3 * w], pty = pos[3 * w + 1], ptz = pos[3 * w + 2];
    float ntx = nor[3 * w], nty = nor[3 * w + 1], ntz = nor[3 * w + 2];
    float4 m = make_float4(0.f, 0.f, 0.f, 0.f);  // relu floor + empty handling

    for (int base = start; base < end; base += 32) {
        int j = base + lane;
        int s = 0;
        float f0 = 0.f, f1 = 0.f, f2 = 0.f, f3 = 0.f;
        if (j < end) {
            s = d_src[j];
            float px = pos[3 * s] - ptx;
            float py = pos[3 * s + 1] - pty;
            float pz = pos[3 * s + 2] - ptz;
            float nsx = nor[3 * s], nsy = nor[3 * s + 1], nsz = nor[3 * s + 2];
            f0 = sqrtf(px * px + py * py + pz * pz);
            f1 = angle3(ntx, nty, ntz, px, py, pz);    // angle(n1, pseudo)
            f2 = angle3(nsx, nsy, nsz, px, py, pz);    // angle(n0, pseudo)
            f3 = angle3(ntx, nty, ntz, nsx, nsy, nsz); // angle(n1, n0)
        }
        int c32 = end - base;
        if (c32 > 32) c32 = 32;
        for (int i = 0; i < c32; i++) {
            int si  = __shfl_sync(0xffffffffu, s, i);
            float g0 = __shfl_sync(0xffffffffu, f0, i);
            float g1 = __shfl_sync(0xffffffffu, f1, i);
            float g2 = __shfl_sync(0xffffffffu, f2, i);
            float g3 = __shfl_sync(0xffffffffu, f3, i);
            uint2 hv = *(const uint2*)&d_pv[(size_t)si * 128 + col];  // 4 halves, 8B
            float2 p01 = __half22float2(*(const __half2*)&hv.x);
            float2 p23 = __half22float2(*(const __half2*)&hv.y);
            float z0 = q.x + p01.x, z1 = q.y + p01.y;
            float z2 = q.z + p23.x, z3 = q.w + p23.y;
            z0 = fmaf(g0, w0.x, z0); z1 = fmaf(g0, w0.y, z1); z2 = fmaf(g0, w0.z, z2); z3 = fmaf(g0, w0.w, z3);
            z0 = fmaf(g1, w1.x, z0); z1 = fmaf(g1, w1.y, z1); z2 = fmaf(g1, w1.z, z2); z3 = fmaf(g1, w1.w, z3);
            z0 = fmaf(g2, w2.x, z0); z1 = fmaf(g2, w2.y, z1); z2 = fmaf(g2, w2.z, z2); z3 = fmaf(g2, w2.w, z3);
            z0 = fmaf(g3, w3.x, z0); z1 = fmaf(g3, w3.y, z1); z2 = fmaf(g3, w3.z, z2); z3 = fmaf(g3, w3.w, z3);
            m.x = fmaxf(m.x, z0); m.y = fmaxf(m.y, z1);
            m.z = fmaxf(m.z, z2); m.w = fmaxf(m.w, z3);
        }
    }
    *(float4*)&d_agg[(size_t)w * 128 + col] = m;
}

// ---------------- gather: out[s] = agg[idx[s]] (0 if no edges), pos_out ----------------
__global__ void k_gather(const float* __restrict__ pos, const int* __restrict__ idx,
                         float* __restrict__ out, int S) {
    int s = blockIdx.x;
    int h = threadIdx.x;  // 128
    int t = idx[s];
    float v = d_cnt[t] ? d_agg[(size_t)t * 128 + h] : 0.f;
    out[(size_t)s * 128 + h] = v;
    if (h < 3) out[(size_t)S * 128 + (size_t)s * 3 + h] = pos[3 * t + h];
}

// ---------------- launch ----------------
extern "C" void kernel_launch(void* const* d_in, const int* in_sizes, int n_in,
                              void* d_out, int out_size) {
    const float *x = 0, *pos = 0, *nor = 0, *Wm = 0, *bv = 0;
    const int *edge = 0, *idx = 0;
    for (int i = 0; i < n_in; i++) {
        int sz = in_sizes[i];
        if (sz == NODES * FEAT) x = (const float*)d_in[i];
        else if (sz == NODES * 3) { if (!pos) pos = (const float*)d_in[i]; else nor = (const float*)d_in[i]; }
        else if (sz == (2 * FEAT + 4) * HID) Wm = (const float*)d_in[i];
        else if (sz == HID) bv = (const float*)d_in[i];
        else if (sz == 2 * EDGES) edge = (const int*)d_in[i];
        else if (sz == SAMP) idx = (const int*)d_in[i];
    }
    const int* ecol = edge;          // e0 (sources)
    const int* erow = edge + EDGES;  // e1 (targets)

    int nb = (NODES + 1023) / 1024;

    k_zero_cnt<<<(NODES + 255) / 256, 256>>>(NODES);
    k_hist<<<(EDGES + 255) / 256, 256>>>(erow, EDGES);
    k_scan1<<<nb, 1024>>>(NODES);
    k_scan2<<<1, 128>>>(nb);
    k_scan3<<<(NODES + 255) / 256, 256>>>(NODES);
    k_scatter<<<(EDGES + 255) / 256, 256>>>(ecol, erow, EDGES);

    cudaFuncSetAttribute(k_gemm_pv, cudaFuncAttributeMaxDynamicSharedMemorySize, GEMM_SMEM);
    cudaFuncSetAttribute(k_gemm_q,  cudaFuncAttributeMaxDynamicSharedMemorySize, GEMM_SMEM);
    k_gemm_pv<<<(NODES + 63) / 64, 256, GEMM_SMEM>>>(x, Wm, NODES);
    k_gemm_q <<<(NODES + 63) / 64, 256, GEMM_SMEM>>>(x, Wm, bv);

    k_agg<<<(NODES + 7) / 8, 256>>>(pos, nor, Wm, NODES);
    k_gather<<<SAMP, 128>>>(pos, idx, (float*)d_out, SAMP);
}

// round 9
// speedup vs baseline: 3.1691x; 1.0347x over previous
#include <cuda_runtime.h>
#include <cuda_fp16.h>
#include <math.h>

// ---------------- problem constants (fixed by the dataset) ----------------
#define NODES 100000
#define FEAT  64
#define EDGES 800000
#define SAMP  25000
#define HID   128

// ---------------- scratch (device globals; no allocation) ----------------
__device__ float  d_q [(size_t)NODES * 128];   // W1^T x + b  (fp32, target nodes only)
__device__ __half d_pv[(size_t)NODES * 128];   // W2^T x      (fp16, per-source, hot stream)
__device__ float  d_agg[(size_t)NODES * 128];  // per-node max-aggregated activations
__device__ int    d_cnt[NODES];
__device__ int    d_off[NODES];
__device__ int    d_cur[NODES];
__device__ int    d_src[EDGES];
__device__ int    d_bsum[128];
__device__ int    d_tlist[NODES];              // compact list of nodes with cnt>0
__device__ int    d_ntl;                       // its length

// ---------------- counting sort of edges by target node ----------------
__global__ void k_zero_cnt(int n) {
    int i = blockIdx.x * blockDim.x + threadIdx.x;
    if (i < n) d_cnt[i] = 0;
    if (i == 0) d_ntl = 0;
}

__global__ void k_hist(const int* __restrict__ row, int E) {
    int i = blockIdx.x * blockDim.x + threadIdx.x;
    if (i < E) atomicAdd(&d_cnt[row[i]], 1);
}

__global__ void k_scan1(int n) {  // per-1024-block inclusive scan, block sums out
    __shared__ int sm[1024];
    int i = blockIdx.x * 1024 + threadIdx.x;
    int v = (i < n) ? d_cnt[i] : 0;
    sm[threadIdx.x] = v;
    __syncthreads();
    for (int d = 1; d < 1024; d <<= 1) {
        int t = 0;
        if (threadIdx.x >= d) t = sm[threadIdx.x - d];
        __syncthreads();
        if (threadIdx.x >= d) sm[threadIdx.x] += t;
        __syncthreads();
    }
    if (i < n) d_off[i] = sm[threadIdx.x];            // inclusive for now
    if (threadIdx.x == 1023) d_bsum[blockIdx.x] = sm[1023];
}

__global__ void k_scan2(int nb) {  // exclusive scan of <=128 block sums (1 block)
    __shared__ int sm[128];
    int t = threadIdx.x;
    int v = (t < nb) ? d_bsum[t] : 0;
    sm[t] = v;
    __syncthreads();
    for (int d = 1; d < 128; d <<= 1) {
        int u = 0;
        if (t >= d) u = sm[t - d];
        __syncthreads();
        if (t >= d) sm[t] += u;
        __syncthreads();
    }
    if (t < nb) d_bsum[t] = sm[t] - v;  // exclusive
}

__global__ void k_scan3(int n) {  // finalize offsets + cursor + compact target list
    int i = blockIdx.x * blockDim.x + threadIdx.x;
    if (i < n) {
        int c = d_cnt[i];
        int e = d_off[i] - c + d_bsum[i >> 10];
        d_off[i] = e;
        d_cur[i] = e;
        if (c > 0) {                       // warp-uniform address -> REDUX-aggregated
            int p = atomicAdd(&d_ntl, 1);
            d_tlist[p] = i;
        }
    }
}

__global__ void k_scatter(const int* __restrict__ col, const int* __restrict__ row, int E) {
    int i = blockIdx.x * blockDim.x + threadIdx.x;
    if (i < E) {
        int t = row[i];
        int p = atomicAdd(&d_cur[t], 1);
        d_src[p] = col[i];
    }
}

// ---------------- GEMM helpers: [tile 64 rows] x [64,128], scalar FFMA ----------------
// smem: As[64 k][68] transposed (17408B) + Bs[64 k][128] (32768B) + tl[64] (256B)
#define GEMM_SMEM ((64 * 68 + 64 * 128 + 64) * 4)

// pv GEMM over ALL nodes: B = W rows [64:128), output fp16 d_pv
__global__ void __launch_bounds__(256)
k_gemm_pv(const float* __restrict__ x, const float* __restrict__ Wm, int N) {
    extern __shared__ float smem[];
    float* As = smem;              // [k*68 + m]
    float* Bs = smem + 64 * 68;    // [k*128 + j]
    int tid = threadIdx.x;
    int row0 = blockIdx.x * 64;

    {   // A tile: 64 rows x 64 feats, transposed
        int r = tid >> 2;
        bool ok = (row0 + r) < N;
        const float* xp = x + (size_t)(row0 + r) * FEAT;
#pragma unroll
        for (int i = 0; i < 4; i++) {
            int c = (tid & 3) * 4 + i * 16;
            float4 v = ok ? *(const float4*)(xp + c) : make_float4(0.f, 0.f, 0.f, 0.f);
            As[(c + 0) * 68 + r] = v.x;
            As[(c + 1) * 68 + r] = v.y;
            As[(c + 2) * 68 + r] = v.z;
            As[(c + 3) * 68 + r] = v.w;
        }
    }
    {   // B tile: W rows [64:128) x 128 cols
#pragma unroll
        for (int i = 0; i < 8; i++) {
            int v = tid + 256 * i;          // 0..2047 float4 slots
            int k = v >> 5;
            int j0 = (v & 31) * 4;
            *(float4*)&Bs[k * 128 + j0] = *(const float4*)(Wm + (64 + k) * 128 + j0);
        }
    }
    __syncthreads();

    int tm = tid >> 5;   // warp id: A reads broadcast
    int tn = tid & 31;   // cols tn*4..tn*4+3
    float acc[8][4];
#pragma unroll
    for (int i = 0; i < 8; i++)
#pragma unroll
        for (int j = 0; j < 4; j++) acc[i][j] = 0.f;

#pragma unroll 4
    for (int k = 0; k < 64; k++) {
        float a[8];
        *(float4*)(a)     = *(const float4*)&As[k * 68 + tm * 8];
        *(float4*)(a + 4) = *(const float4*)&As[k * 68 + tm * 8 + 4];
        float4 b4 = *(const float4*)&Bs[k * 128 + tn * 4];
#pragma unroll
        for (int i = 0; i < 8; i++) {
            acc[i][0] = fmaf(a[i], b4.x, acc[i][0]);
            acc[i][1] = fmaf(a[i], b4.y, acc[i][1]);
            acc[i][2] = fmaf(a[i], b4.z, acc[i][2]);
            acc[i][3] = fmaf(a[i], b4.w, acc[i][3]);
        }
    }

#pragma unroll
    for (int i = 0; i < 8; i++) {
        int r = row0 + tm * 8 + i;
        if (r < N) {
            __half2 h0 = __floats2half2_rn(acc[i][0], acc[i][1]);
            __half2 h1 = __floats2half2_rn(acc[i][2], acc[i][3]);
            *(uint2*)&d_pv[(size_t)r * 128 + tn * 4] = make_uint2(
                *(unsigned*)&h0, *(unsigned*)&h1);
        }
    }
}

// q GEMM over target-node list: B = W rows [0:64), + bias, output fp32 d_q
__global__ void __launch_bounds__(256)
k_gemm_q(const float* __restrict__ x, const float* __restrict__ Wm,
         const float* __restrict__ bv) {
    int ntl = d_ntl;
    int row0 = blockIdx.x * 64;
    if (row0 >= ntl) return;
    extern __shared__ float smem[];
    float* As = smem;
    float* Bs = smem + 64 * 68;
    int*   tl = (int*)(smem + 64 * 68 + 64 * 128);
    int tid = threadIdx.x;

    if (tid < 64) tl[tid] = (row0 + tid < ntl) ? d_tlist[row0 + tid] : -1;
    __syncthreads();

    {   // A tile via row indirection
        int r = tid >> 2;
        int row = tl[r];
        bool ok = row >= 0;
        const float* xp = x + (size_t)(ok ? row : 0) * FEAT;
#pragma unroll
        for (int i = 0; i < 4; i++) {
            int c = (tid & 3) * 4 + i * 16;
            float4 v = ok ? *(const float4*)(xp + c) : make_float4(0.f, 0.f, 0.f, 0.f);
            As[(c + 0) * 68 + r] = v.x;
            As[(c + 1) * 68 + r] = v.y;
            As[(c + 2) * 68 + r] = v.z;
            As[(c + 3) * 68 + r] = v.w;
        }
    }
    {   // B tile: W rows [0:64)
#pragma unroll
        for (int i = 0; i < 8; i++) {
            int v = tid + 256 * i;
            int k = v >> 5;
            int j0 = (v & 31) * 4;
            *(float4*)&Bs[k * 128 + j0] = *(const float4*)(Wm + k * 128 + j0);
        }
    }
    __syncthreads();

    int tm = tid >> 5;
    int tn = tid & 31;
    float acc[8][4];
#pragma unroll
    for (int i = 0; i < 8; i++)
#pragma unroll
        for (int j = 0; j < 4; j++) acc[i][j] = 0.f;

#pragma unroll 4
    for (int k = 0; k < 64; k++) {
        float a[8];
        *(float4*)(a)     = *(const float4*)&As[k * 68 + tm * 8];
        *(float4*)(a + 4) = *(const float4*)&As[k * 68 + tm * 8 + 4];
        float4 b4 = *(const float4*)&Bs[k * 128 + tn * 4];
#pragma unroll
        for (int i = 0; i < 8; i++) {
            acc[i][0] = fmaf(a[i], b4.x, acc[i][0]);
            acc[i][1] = fmaf(a[i], b4.y, acc[i][1]);
            acc[i][2] = fmaf(a[i], b4.z, acc[i][2]);
            acc[i][3] = fmaf(a[i], b4.w, acc[i][3]);
        }
    }

    float4 bias = *(const float4*)&bv[tn * 4];
#pragma unroll
    for (int i = 0; i < 8; i++) {
        int row = tl[tm * 8 + i];
        if (row >= 0) {
            float4 v = make_float4(acc[i][0] + bias.x, acc[i][1] + bias.y,
                                   acc[i][2] + bias.z, acc[i][3] + bias.w);
            *(float4*)&d_q[(size_t)row * 128 + tn * 4] = v;
        }
    }
}

// ---------------- edge aggregation: one warp per target node ----------------
__device__ __forceinline__ float angle3(float ax, float ay, float az,
                                        float bx, float by, float bz) {
    float cx = ay * bz - az * by;
    float cy = az * bx - ax * bz;
    float cz = ax * by - ay * bx;
    float cn = sqrtf(cx * cx + cy * cy + cz * cz);
    float d = ax * bx + ay * by + az * bz;
    return atan2f(cn, d);
}

__global__ void k_agg(const float* __restrict__ pos, const float* __restrict__ nor,
                      const float* __restrict__ Wm, int N) {
    int w = (blockIdx.x * blockDim.x + threadIdx.x) >> 5;
    if (w >= N) return;
    int cnt = d_cnt[w];
    if (cnt == 0) return;
    int lane = threadIdx.x & 31;
    int start = d_off[w];
    int end = start + cnt;
    int col = lane * 4;

    float4 q  = *(const float4*)&d_q[(size_t)w * 128 + col];    // includes bias
    float4 w0 = *(const float4*)&Wm[128 * 128 + col];           // ppf weight rows
    float4 w1 = *(const float4*)&Wm[129 * 128 + col];
    float4 w2 = *(const float4*)&Wm[130 * 128 + col];
    float4 w3 = *(const float4*)&Wm[131 * 128 + col];
    float ptx = pos[3 * w], pty = pos[3 * w + 1], ptz = pos[3 * w + 2];
    float ntx = nor[3 * w], nty = nor[3 * w + 1], ntz = nor[3 * w + 2];
    float4 m = make_float4(0.f, 0.f, 0.f, 0.f);  // relu floor + empty handling

    for (int base = start; base < end; base += 32) {
        int j = base + lane;
        int s = 0;
        float f0 = 0.f, f1 = 0.f, f2 = 0.f, f3 = 0.f;
        if (j < end) {
            s = d_src[j];
            float px = pos[3 * s] - ptx;
            float py = pos[3 * s + 1] - pty;
            float pz = pos[3 * s + 2] - ptz;
            float nsx = nor[3 * s], nsy = nor[3 * s + 1], nsz = nor[3 * s + 2];
            f0 = sqrtf(px * px + py * py + pz * pz);
            f1 = angle3(ntx, nty, ntz, px, py, pz);    // angle(n1, pseudo)
            f2 = angle3(nsx, nsy, nsz, px, py, pz);    // angle(n0, pseudo)
            f3 = angle3(ntx, nty, ntz, nsx, nsy, nsz); // angle(n1, n0)
        }
        int c32 = end - base;
        if (c32 > 32) c32 = 32;
        for (int i = 0; i < c32; i++) {
            int si  = __shfl_sync(0xffffffffu, s, i);
            float g0 = __shfl_sync(0xffffffffu, f0, i);
            float g1 = __shfl_sync(0xffffffffu, f1, i);
            float g2 = __shfl_sync(0xffffffffu, f2, i);
            float g3 = __shfl_sync(0xffffffffu, f3, i);
            uint2 hv = *(const uint2*)&d_pv[(size_t)si * 128 + col];  // 4 halves, 8B
            float2 p01 = __half22float2(*(const __half2*)&hv.x);
            float2 p23 = __half22float2(*(const __half2*)&hv.y);
            float z0 = q.x + p01.x, z1 = q.y + p01.y;
            float z2 = q.z + p23.x, z3 = q.w + p23.y;
            z0 = fmaf(g0, w0.x, z0); z1 = fmaf(g0, w0.y, z1); z2 = fmaf(g0, w0.z, z2); z3 = fmaf(g0, w0.w, z3);
            z0 = fmaf(g1, w1.x, z0); z1 = fmaf(g1, w1.y, z1); z2 = fmaf(g1, w1.z, z2); z3 = fmaf(g1, w1.w, z3);
            z0 = fmaf(g2, w2.x, z0); z1 = fmaf(g2, w2.y, z1); z2 = fmaf(g2, w2.z, z2); z3 = fmaf(g2, w2.w, z3);
            z0 = fmaf(g3, w3.x, z0); z1 = fmaf(g3, w3.y, z1); z2 = fmaf(g3, w3.z, z2); z3 = fmaf(g3, w3.w, z3);
            m.x = fmaxf(m.x, z0); m.y = fmaxf(m.y, z1);
            m.z = fmaxf(m.z, z2); m.w = fmaxf(m.w, z3);
        }
    }
    *(float4*)&d_agg[(size_t)w * 128 + col] = m;
}

// ---------------- gather: out[s] = agg[idx[s]] (0 if no edges), pos_out ----------------
__global__ void k_gather(const float* __restrict__ pos, const int* __restrict__ idx,
                         float* __restrict__ out, int S) {
    int s = blockIdx.x;
    int h = threadIdx.x;  // 128
    int t = idx[s];
    float v = d_cnt[t] ? d_agg[(size_t)t * 128 + h] : 0.f;
    out[(size_t)s * 128 + h] = v;
    if (h < 3) out[(size_t)S * 128 + (size_t)s * 3 + h] = pos[3 * t + h];
}

// ---------------- launch (fork-join: gemm_pv || sort chain, gemm_q || scatter) ----------------
extern "C" void kernel_launch(void* const* d_in, const int* in_sizes, int n_in,
                              void* d_out, int out_size) {
    const float *x = 0, *pos = 0, *nor = 0, *Wm = 0, *bv = 0;
    const int *edge = 0, *idx = 0;
    for (int i = 0; i < n_in; i++) {
        int sz = in_sizes[i];
        if (sz == NODES * FEAT) x = (const float*)d_in[i];
        else if (sz == NODES * 3) { if (!pos) pos = (const float*)d_in[i]; else nor = (const float*)d_in[i]; }
        else if (sz == (2 * FEAT + 4) * HID) Wm = (const float*)d_in[i];
        else if (sz == HID) bv = (const float*)d_in[i];
        else if (sz == 2 * EDGES) edge = (const int*)d_in[i];
        else if (sz == SAMP) idx = (const int*)d_in[i];
    }
    const int* ecol = edge;          // e0 (sources)
    const int* erow = edge + EDGES;  // e1 (targets)

    // one-time infra init (first call is the uncaptured correctness run;
    // capture calls only replay the same launches -> deterministic work)
    static cudaStream_t sB = 0, sC = 0;
    static cudaEvent_t eFork = 0, ePv = 0, eS3 = 0, eQ = 0;
    if (!sB) {
        cudaStreamCreateWithFlags(&sB, cudaStreamNonBlocking);
        cudaStreamCreateWithFlags(&sC, cudaStreamNonBlocking);
        cudaEventCreateWithFlags(&eFork, cudaEventDisableTiming);
        cudaEventCreateWithFlags(&ePv,   cudaEventDisableTiming);
        cudaEventCreateWithFlags(&eS3,   cudaEventDisableTiming);
        cudaEventCreateWithFlags(&eQ,    cudaEventDisableTiming);
        cudaFuncSetAttribute(k_gemm_pv, cudaFuncAttributeMaxDynamicSharedMemorySize, GEMM_SMEM);
        cudaFuncSetAttribute(k_gemm_q,  cudaFuncAttributeMaxDynamicSharedMemorySize, GEMM_SMEM);
    }

    int nb = (NODES + 1023) / 1024;

    // fork: gemm_pv on sB, independent of the sort chain
    cudaEventRecord(eFork, 0);
    cudaStreamWaitEvent(sB, eFork, 0);
    k_gemm_pv<<<(NODES + 63) / 64, 256, GEMM_SMEM, sB>>>(x, Wm, NODES);
    cudaEventRecord(ePv, sB);

    // sort chain on the main stream
    k_zero_cnt<<<(NODES + 255) / 256, 256>>>(NODES);
    k_hist<<<(EDGES + 255) / 256, 256>>>(erow, EDGES);
    k_scan1<<<nb, 1024>>>(NODES);
    k_scan2<<<1, 128>>>(nb);
    k_scan3<<<(NODES + 255) / 256, 256>>>(NODES);
    cudaEventRecord(eS3, 0);

    // gemm_q on sC (needs only scan3's tlist), overlaps with scatter
    cudaStreamWaitEvent(sC, eS3, 0);
    k_gemm_q<<<(NODES + 63) / 64, 256, GEMM_SMEM, sC>>>(x, Wm, bv);
    cudaEventRecord(eQ, sC);

    k_scatter<<<(EDGES + 255) / 256, 256>>>(ecol, erow, EDGES);

    // join: agg needs scatter (main), gemm_pv (sB), gemm_q (sC)
    cudaStreamWaitEvent(0, ePv, 0);
    cudaStreamWaitEvent(0, eQ, 0);
    k_agg<<<(NODES + 7) / 8, 256>>>(pos, nor, Wm, NODES);
    k_gather<<<SAMP, 128>>>(pos, idx, (float*)d_out, SAMP);
}